// round 1
// baseline (speedup 1.0000x reference)
#include <cuda_runtime.h>
#include <cuda_bf16.h>
#include <cstdint>

// Problem constants (fixed shapes for this instance)
#define B 4
#define C 64
#define C2 32
#define HW 4096            // 64*64
#define GROUP 8
#define NG 4               // C2 / GROUP
#define NROWS 65536        // B * HW * NG
#define NSAMP 2048
#define NCHUNK 2
#define CHUNK_N 1024       // NSAMP / NCHUNK
#define YK 18              // 16 fma terms + y16 + pad (ull units per sample)
#define LOGVAR_MIN (-30.0f)
#define LOGVAR_MAX (20.0f)

// Scratch (no allocations allowed -> device globals)
__device__ unsigned long long g_Ydup[NSAMP * YK];   // duplicated {v,v} pairs
__device__ float g_pbest[NCHUNK * NROWS];
__device__ int   g_pidx [NCHUNK * NROWS];

// ---------- f32x2 helpers ----------
__device__ __forceinline__ unsigned long long fma2(unsigned long long a,
                                                   unsigned long long b,
                                                   unsigned long long c) {
    unsigned long long d;
    asm("fma.rn.f32x2 %0, %1, %2, %3;" : "=l"(d) : "l"(a), "l"(b), "l"(c));
    return d;
}
__device__ __forceinline__ unsigned long long pk2(float lo, float hi) {
    unsigned long long u;
    asm("mov.b64 %0, {%1, %2};" : "=l"(u) : "f"(lo), "f"(hi));
    return u;
}
__device__ __forceinline__ void upk(unsigned long long u, float& lo, float& hi) {
    asm("mov.b64 {%0, %1}, %2;" : "=f"(lo), "=f"(hi) : "l"(u));
}

// ---------- Kernel A: build duplicated sample table ----------
// y[k] for k=0..7: s2_g ; k=8..15: s_g ; k=16: 0.5*sum(s2) ; k=17: pad
__global__ void prep_samples_kernel(const float* __restrict__ prior) {
    int n = blockIdx.x * blockDim.x + threadIdx.x;
    if (n >= NSAMP) return;
    const float4* pr = reinterpret_cast<const float4*>(prior + n * GROUP);
    float4 s0 = pr[0], s1 = pr[1];
    float s[8] = {s0.x, s0.y, s0.z, s0.w, s1.x, s1.y, s1.z, s1.w};
    float s2[8];
    float sum2 = 0.f;
#pragma unroll
    for (int g = 0; g < 8; g++) { s2[g] = s[g] * s[g]; sum2 += s2[g]; }
    unsigned long long* d = g_Ydup + n * YK;
#pragma unroll
    for (int g = 0; g < 8; g++) d[g] = pk2(s2[g], s2[g]);
#pragma unroll
    for (int g = 0; g < 8; g++) d[8 + g] = pk2(s[g], s[g]);
    d[16] = pk2(0.5f * sum2, 0.5f * sum2);
    d[17] = 0ull;
}

// ---------- Kernel B: score + partial argmax ----------
// grid = 128 blocks: blockIdx = rblk*2 + chunk. Each block: 1024 rows x 1024 samples.
// 256 threads, 4 rows/thread, rows paired into f32x2 lanes.
__global__ __launch_bounds__(256, 1)
void score_kernel(const float* __restrict__ z) {
    extern __shared__ unsigned long long sY[];   // CHUNK_N * YK ull = 147456 B

    const int chunk = blockIdx.x & 1;
    const int rblk  = blockIdx.x >> 1;
    const int tid   = threadIdx.x;

    // cooperative copy of this chunk's duplicated table into smem
    {
        const ulonglong2* src =
            reinterpret_cast<const ulonglong2*>(g_Ydup + (size_t)chunk * CHUNK_N * YK);
        ulonglong2* dst = reinterpret_cast<ulonglong2*>(sY);
        const int total = CHUNK_N * YK / 2;   // 9216
#pragma unroll 4
        for (int i = tid; i < total; i += 256) dst[i] = src[i];
    }

    // per-thread rows and coefficient packing
    int rows[4];
#pragma unroll
    for (int j = 0; j < 4; j++) rows[j] = rblk * 1024 + tid + j * 256;

    float av[4][8], cv[4][8];
#pragma unroll
    for (int j = 0; j < 4; j++) {
        int r = rows[j];
        int b = r >> 14;
        int rem = r & 16383;
        int p = rem >> 2;
        int ns = rem & 3;
        const float* zb = z + ((size_t)b * C) * HW + p;
#pragma unroll
        for (int g = 0; g < 8; g++) {
            int ch = g * 4 + ns;
            float mu = __ldg(zb + (size_t)ch * HW);
            float lv = __ldg(zb + (size_t)(ch + C2) * HW);
            lv = fminf(fmaxf(lv, LOGVAR_MIN), LOGVAR_MAX);
            float iv = expf(-lv);              // 1/var
            av[j][g] = -0.5f * iv;
            cv[j][g] = mu * iv;
        }
    }

    unsigned long long x0[16], x1[16];
#pragma unroll
    for (int g = 0; g < 8; g++) {
        x0[g]     = pk2(av[0][g], av[1][g]);
        x0[8 + g] = pk2(cv[0][g], cv[1][g]);
        x1[g]     = pk2(av[2][g], av[3][g]);
        x1[8 + g] = pk2(cv[2][g], cv[3][g]);
    }

    __syncthreads();

    const float NEG_INF = __int_as_float(0xff800000);
    float best[4] = {NEG_INF, NEG_INF, NEG_INF, NEG_INF};
    int   bidx[4] = {0, 0, 0, 0};

#pragma unroll 2
    for (int n = 0; n < CHUNK_N; n++) {
        const ulonglong2* yp = reinterpret_cast<const ulonglong2*>(sY + n * YK);
        // broadcast LDS.128 loads (all lanes same address -> conflict-free)
        ulonglong2 q0 = yp[0], q1 = yp[1], q2 = yp[2], q3 = yp[3];
        ulonglong2 q4 = yp[4], q5 = yp[5], q6 = yp[6], q7 = yp[7];
        ulonglong2 q8 = yp[8];
        unsigned long long yd[16] = {q0.x, q0.y, q1.x, q1.y, q2.x, q2.y, q3.x, q3.y,
                                     q4.x, q4.y, q5.x, q5.y, q6.x, q6.y, q7.x, q7.y};
        unsigned long long acc0 = q8.x;   // init with y16 = 0.5*sum(s2)
        unsigned long long acc1 = q8.x;
#pragma unroll
        for (int k = 0; k < 16; k++) {
            acc0 = fma2(x0[k], yd[k], acc0);
            acc1 = fma2(x1[k], yd[k], acc1);
        }
        float sa, sb, sc, sd;
        upk(acc0, sa, sb);
        upk(acc1, sc, sd);
        if (sa > best[0]) { best[0] = sa; bidx[0] = n; }
        if (sb > best[1]) { best[1] = sb; bidx[1] = n; }
        if (sc > best[2]) { best[2] = sc; bidx[2] = n; }
        if (sd > best[3]) { best[3] = sd; bidx[3] = n; }
    }

    const int nbase = chunk * CHUNK_N;
#pragma unroll
    for (int j = 0; j < 4; j++) {
        g_pbest[(size_t)chunk * NROWS + rows[j]] = best[j];
        g_pidx [(size_t)chunk * NROWS + rows[j]] = nbase + bidx[j];
    }
}

// ---------- Kernel C: merge chunks + scatter outputs ----------
// out layout (float32): [zhat (B,32,64,64) = 524288] then [indices (B,4,64,64) = 65536]
__global__ void finalize_kernel(const float* __restrict__ prior,
                                float* __restrict__ out) {
    int r = blockIdx.x * blockDim.x + threadIdx.x;
    if (r >= NROWS) return;
    float s0 = g_pbest[r];
    float s1 = g_pbest[NROWS + r];
    int bi = (s1 > s0) ? g_pidx[NROWS + r] : g_pidx[r];  // tie -> lower chunk (first occurrence)

    int b = r >> 14;
    int rem = r & 16383;
    int p = rem >> 2;
    int ns = rem & 3;

    const float* pr = prior + (size_t)bi * GROUP;
    float* zo = out + ((size_t)b * C2) * HW + p;
#pragma unroll
    for (int g = 0; g < 8; g++) {
        zo[(size_t)(g * 4 + ns) * HW] = __ldg(pr + g);
    }
    out[(size_t)B * C2 * HW + (((size_t)b * NG + ns) * HW + p)] = (float)bi;
}

extern "C" void kernel_launch(void* const* d_in, const int* in_sizes, int n_in,
                              void* d_out, int out_size) {
    const float* z     = (const float*)d_in[0];
    const float* prior = (const float*)d_in[1];
    float* out = (float*)d_out;

    static bool attr_set = false;
    // setting the attribute is idempotent and not a stream op; safe under capture
    cudaFuncSetAttribute(score_kernel, cudaFuncAttributeMaxDynamicSharedMemorySize,
                         CHUNK_N * YK * (int)sizeof(unsigned long long));

    prep_samples_kernel<<<(NSAMP + 255) / 256, 256>>>(prior);
    score_kernel<<<128, 256, CHUNK_N * YK * sizeof(unsigned long long)>>>(z);
    finalize_kernel<<<(NROWS + 255) / 256, 256>>>(prior, out);
    (void)attr_set; (void)in_sizes; (void)n_in; (void)out_size;
}